// round 14
// baseline (speedup 1.0000x reference)
#include <cuda_runtime.h>
#include <cstdint>

// ---------------------------------------------------------------------------
// GeoEEGSNN forward: B=64, C=64, T=1024, Tq=256. 3 launches:
//   k_front : [0..383] encode (ratio trick, ex2.approx, f32x2 packed math)
//             [384..639] curv/tang mapper (pool4 first, f32x2)  [1 wave]
//   k_conv  : inline BN2 finalize + BN2+ELU + dw15 + pw(24->32) -> g_pw
//   k_scan  : own-slice BN1 partials + device barrier + finalize +
//             prelif + parallel cs/ts + serial m + FC
// ---------------------------------------------------------------------------

#define B 64
#define CDIM 64
#define T 1024
#define BT (B*T)           // 65536
#define TQ 256
#define NCTA_ENC 128       // partial blocks per feature
#define LOG2E 1.4426950408889634f

typedef unsigned long long u64;

__device__ float g_s [24 * BT];
__device__ float g_pw[32 * BT];
__device__ float g_curv[B * TQ * 32];   // [b][tq][o]
__device__ float g_tang[B * TQ * 32];
__device__ float g_ep_sum[24 * NCTA_ENC], g_ep_sq[24 * NCTA_ENC];
__device__ float g_bps[B * 32], g_bpq[B * 32];   // per-b BN1 partials
__device__ int   g_ctr1 = 0, g_ctr2 = 0;

// Raw MUFU exp2 (what __expf lowers to after its x*log2e pre-multiply).
__device__ __forceinline__ float fex2(float x) {
    float r;
    asm("ex2.approx.ftz.f32 %0, %1;" : "=f"(r) : "f"(x));
    return r;
}

__device__ __forceinline__ float eluf(float x) {
    return x > 0.0f ? x : (__expf(x) - 1.0f);
}

// ---- packed f32x2 helpers (per-lane rounding == scalar fmaf) -------------
__device__ __forceinline__ u64 pk2(float lo, float hi) {
    u64 r; asm("mov.b64 %0, {%1, %2};" : "=l"(r) : "f"(lo), "f"(hi)); return r;
}
__device__ __forceinline__ void upk2(u64 v, float& lo, float& hi) {
    asm("mov.b64 {%0, %1}, %2;" : "=f"(lo), "=f"(hi) : "l"(v));
}
__device__ __forceinline__ u64 fma2(u64 a, u64 b, u64 c) {
    u64 d; asm("fma.rn.f32x2 %0, %1, %2, %3;" : "=l"(d) : "l"(a), "l"(b), "l"(c)); return d;
}
__device__ __forceinline__ u64 mul2(u64 a, u64 b) {
    u64 d; asm("mul.rn.f32x2 %0, %1, %2;" : "=l"(d) : "l"(a), "l"(b)); return d;
}
__device__ __forceinline__ u64 add2(u64 a, u64 b) {
    u64 d; asm("add.rn.f32x2 %0, %1, %2;" : "=l"(d) : "l"(a), "l"(b)); return d;
}

// ---------------------------------------------------------------------------
// K_front: fat kernel. Blocks [0,384): encode (2 t/thread, packed);
// [384,640): mapper (packed). Shared aliased. occ 5 -> 640 fits one wave.
// ---------------------------------------------------------------------------
__global__ void __launch_bounds__(256, 5)
k_front(const float* __restrict__ xb,
        const float* __restrict__ curvW,
        const float* __restrict__ tangW,
        const float* __restrict__ mu,
        const float* __restrict__ sigma,
        const float* __restrict__ spatialW) {
    __shared__ __align__(16) char smem[16896];

    if (blockIdx.x < 384) {
        // ---------------- encode ----------------
        // sdup[c][2p]   = (w_p.x, w_p.x)  duplicated pairs for f32x2
        // sdup[c][2p+1] = (w_p.y, w_p.y)
        float2 (*sdup)[8]  = (float2(*)[8])smem;             // 4096 B
        float  (*red_s)[8] = (float(*)[8])(smem + 4096);
        float  (*red_q)[8] = (float(*)[8])(smem + 4352);

        int f   = blockIdx.x / 128;
        int blk = blockIdx.x - f * 128;
        int b     = blk >> 1;
        int thalf = blk & 1;

        float smu[4], sg[4];
#pragma unroll
        for (int p = 0; p < 4; p++) { smu[p] = __ldg(mu + p); sg[p] = __ldg(sigma + p); }
        float d = smu[1] - smu[0];
        bool uni = (fabsf((smu[2] - smu[1]) - d) <= 1e-5f * fmaxf(1.0f, fabsf(d))) &&
                   (fabsf((smu[3] - smu[2]) - d) <= 1e-5f * fmaxf(1.0f, fabsf(d))) &&
                   (fabsf(sg[1] - sg[0]) <= 1e-6f) &&
                   (fabsf(sg[2] - sg[0]) <= 1e-6f) &&
                   (fabsf(sg[3] - sg[0]) <= 1e-6f);
        float q    = -1.0f / (2.0f * sg[0] * sg[0] + 1e-6f);
        float m0   = smu[0];
        float n2qd = -2.0f * q * d;
        float q2    = q * LOG2E;
        float n2qd2 = n2qd * LOG2E;

        {
            int i = threadIdx.x;             // 256 = 4p x 64c
            int p = i >> 6, c = i & 63;
            int g = f * 4 + p;
            float cp = uni ? expf(q * (float)(p * p) * d * d) : 1.0f;
            float wx = spatialW[(g * 2 + 0) * 64 + c] * cp;
            float wy = spatialW[(g * 2 + 1) * 64 + c] * cp;
            sdup[c][2 * p + 0] = make_float2(wx, wx);
            sdup[c][2 * p + 1] = make_float2(wy, wy);
        }
        __syncthreads();

        int t = thalf * 512 + threadIdx.x * 2;

        u64 acc[8];
#pragma unroll
        for (int i = 0; i < 8; i++) acc[i] = 0ull;

        const float* xp = xb + ((size_t)(b * 3 + f) * CDIM) * T + t;

        if (uni) {
            u64 m0n = pk2(-m0, -m0);
            u64 q22 = pk2(q2, q2);
            u64 n22 = pk2(n2qd2, n2qd2);
#pragma unroll 4
            for (int c = 0; c < CDIM; c++) {
                u64 xv = *(const u64*)(xp + (size_t)c * T);
                u64 dx = add2(xv, m0n);
                u64 qa = mul2(mul2(dx, dx), q22);
                u64 ra = mul2(dx, n22);
                float qa0, qa1, ra0, ra1;
                upk2(qa, qa0, qa1);
                upk2(ra, ra0, ra1);
                u64 pa = pk2(fex2(qa0), fex2(qa1));
                u64 pr = pk2(fex2(ra0), fex2(ra1));
                const ulonglong2* wp = (const ulonglong2*)&sdup[c][0];
                ulonglong2 w0 = wp[0];
                ulonglong2 w1 = wp[1];
                ulonglong2 w2 = wp[2];
                ulonglong2 w3 = wp[3];
                acc[0] = fma2(pa, w0.x, acc[0]);
                acc[1] = fma2(pa, w0.y, acc[1]);
                pa = mul2(pa, pr);
                acc[2] = fma2(pa, w1.x, acc[2]);
                acc[3] = fma2(pa, w1.y, acc[3]);
                pa = mul2(pa, pr);
                acc[4] = fma2(pa, w2.x, acc[4]);
                acc[5] = fma2(pa, w2.y, acc[5]);
                pa = mul2(pa, pr);
                acc[6] = fma2(pa, w3.x, acc[6]);
                acc[7] = fma2(pa, w3.y, acc[7]);
            }
        } else {
            float sneg[4];
#pragma unroll
            for (int p = 0; p < 4; p++) sneg[p] = -1.0f / (2.0f * sg[p] * sg[p] + 1e-6f);
            float a0s[8], a1s[8];
#pragma unroll
            for (int i = 0; i < 8; i++) { a0s[i] = 0.0f; a1s[i] = 0.0f; }
#pragma unroll 2
            for (int c = 0; c < CDIM; c++) {
                float2 xv = *(const float2*)(xp + (size_t)c * T);
#pragma unroll
                for (int p = 0; p < 4; p++) {
                    float wx = sdup[c][2 * p + 0].x;
                    float wy = sdup[c][2 * p + 1].x;
                    float dx0 = xv.x - smu[p];
                    float dx1 = xv.y - smu[p];
                    float e0 = expf(dx0 * dx0 * sneg[p]);
                    float e1 = expf(dx1 * dx1 * sneg[p]);
                    a0s[p*2+0] = fmaf(e0, wx, a0s[p*2+0]);
                    a0s[p*2+1] = fmaf(e0, wy, a0s[p*2+1]);
                    a1s[p*2+0] = fmaf(e1, wx, a1s[p*2+0]);
                    a1s[p*2+1] = fmaf(e1, wy, a1s[p*2+1]);
                }
            }
#pragma unroll
            for (int i = 0; i < 8; i++) acc[i] = pk2(a0s[i], a1s[i]);
        }

#pragma unroll
        for (int cc = 0; cc < 8; cc++)
            *(u64*)(g_s + (size_t)(f * 8 + cc) * BT + b * T + t) = acc[cc];

        int w = threadIdx.x >> 5, lane = threadIdx.x & 31;
#pragma unroll
        for (int cc = 0; cc < 8; cc++) {
            float a0, a1;
            upk2(acc[cc], a0, a1);
            float s  = a0 + a1;
            float qv = a0 * a0 + a1 * a1;
#pragma unroll
            for (int off = 16; off > 0; off >>= 1) {
                s  += __shfl_xor_sync(0xffffffffu, s, off);
                qv += __shfl_xor_sync(0xffffffffu, qv, off);
            }
            if (lane == 0) { red_s[w][cc] = s; red_q[w][cc] = qv; }
        }
        __syncthreads();
        if (threadIdx.x < 8) {
            float S = 0.0f, Q = 0.0f;
#pragma unroll
            for (int ww = 0; ww < 8; ww++) { S += red_s[ww][threadIdx.x]; Q += red_q[ww][threadIdx.x]; }
            g_ep_sum[(f * 8 + threadIdx.x) * NCTA_ENC + blk] = S;
            g_ep_sq [(f * 8 + threadIdx.x) * NCTA_ENC + blk] = Q;
        }
    } else {
        // ---------------- mapper (packed o-pairs) ----------------
        float (*wT)[64][32] = (float(*)[64][32])smem;   // 16KB

        int mbid = blockIdx.x - 384;
        for (int i = threadIdx.x; i < 2048; i += 256) {
            int o = i >> 6, c = i & 63;
            wT[0][c][o] = curvW[i];
            wT[1][c][o] = tangW[i];
        }
        __syncthreads();

        int b    = mbid >> 2;
        int tq   = (mbid & 3) * 64 + (threadIdx.x & 63);
        int sub  = threadIdx.x >> 6;
        int feat = sub >> 1;
        int ob   = (sub & 1) * 16;

        u64 acc2[8];
#pragma unroll
        for (int j = 0; j < 8; j++) acc2[j] = 0ull;

        const float* x = xb + ((size_t)(b * 3 + 1 + feat) * CDIM) * T + tq * 4;

#pragma unroll 4
        for (int c = 0; c < CDIM; c++) {
            float4 v = *(const float4*)(x + (size_t)c * T);
            float p = (v.x + v.y + v.z + v.w) * 0.25f;
            u64 pp = pk2(p, p);
            const ulonglong2* wq = (const ulonglong2*)&wT[feat][c][ob];
            ulonglong2 wa = wq[0];   // o+0..3 as two packed pairs
            ulonglong2 wb = wq[1];   // o+4..7
            ulonglong2 wc = wq[2];   // o+8..11
            ulonglong2 wd = wq[3];   // o+12..15
            acc2[0] = fma2(pp, wa.x, acc2[0]);
            acc2[1] = fma2(pp, wa.y, acc2[1]);
            acc2[2] = fma2(pp, wb.x, acc2[2]);
            acc2[3] = fma2(pp, wb.y, acc2[3]);
            acc2[4] = fma2(pp, wc.x, acc2[4]);
            acc2[5] = fma2(pp, wc.y, acc2[5]);
            acc2[6] = fma2(pp, wd.x, acc2[6]);
            acc2[7] = fma2(pp, wd.y, acc2[7]);
        }

        float* dst = (feat == 0 ? g_curv : g_tang) +
                     (size_t)b * (TQ * 32) + (size_t)tq * 32 + ob;
#pragma unroll
        for (int j = 0; j < 4; j++) {
            ulonglong2 st;
            st.x = acc2[2 * j + 0];
            st.y = acc2[2 * j + 1];
            *(ulonglong2*)(dst + j * 4) = st;
        }
    }
}

// ---------------------------------------------------------------------------
// K_conv: inline BN2 finalize + BN2+ELU + dw15 + pw(24->32).
// No min-blocks clause: 48 regs / 5 blocks-per-SM natural, no spills.
// ---------------------------------------------------------------------------
__global__ void __launch_bounds__(256)
k_conv(const float* __restrict__ dwW,
       const float* __restrict__ pwW,
       const float* __restrict__ bn2_g,
       const float* __restrict__ bn2_b) {
    __shared__ float sh[24][80];
    __shared__ float sdw[24][16];
    __shared__ float spw[32][24];
    __shared__ float dwv[24][68];
    __shared__ float ssc2[24], ssh2[24];

    int b   = blockIdx.x >> 4;
    int t0  = (blockIdx.x & 15) * 64;
    int tid = threadIdx.x;
    int wid = tid >> 5, lane = tid & 31;

    for (int i = tid; i < 360; i += 256) sdw[i / 15][i % 15] = dwW[i];
    for (int i = tid; i < 768; i += 256) spw[i / 24][i % 24] = pwW[i];

#pragma unroll
    for (int cc = 0; cc < 3; cc++) {
        int ch = wid * 3 + cc;
        const float* ps = g_ep_sum + ch * NCTA_ENC;
        const float* pq = g_ep_sq  + ch * NCTA_ENC;
        float s  = (ps[lane] + ps[lane + 32]) + (ps[lane + 64] + ps[lane + 96]);
        float qv = (pq[lane] + pq[lane + 32]) + (pq[lane + 64] + pq[lane + 96]);
#pragma unroll
        for (int off = 16; off > 0; off >>= 1) {
            s  += __shfl_xor_sync(0xffffffffu, s, off);
            qv += __shfl_xor_sync(0xffffffffu, qv, off);
        }
        if (lane == 0) {
            float mean = s * (1.0f / BT);
            float var  = fmaxf(qv * (1.0f / BT) - mean * mean, 0.0f);
            float sc   = __ldg(bn2_g + ch) * rsqrtf(var + 1e-5f);
            ssc2[ch] = sc;
            ssh2[ch] = __ldg(bn2_b + ch) - mean * sc;
        }
    }
    __syncthreads();

    for (int i = tid; i < 24 * 78; i += 256) {
        int ch = i / 78, j = i % 78;
        int t = t0 + j - 7;
        float v = 0.0f;
        if (t >= 0 && t < T) {
            float raw = g_s[(size_t)ch * BT + b * T + t];
            v = eluf(fmaf(raw, ssc2[ch], ssh2[ch]));
        }
        sh[ch][j] = v;
    }
    __syncthreads();

    {
        int tp = tid & 31;
        int cg = tid >> 5;
#pragma unroll
        for (int cc = 0; cc < 3; cc++) {
            int ch = cg * 3 + cc;
            float s[18];
#pragma unroll
            for (int j = 0; j < 9; j++) {
                float2 v = *(const float2*)&sh[ch][2 * tp + 2 * j];
                s[2*j] = v.x; s[2*j+1] = v.y;
            }
            float a0 = 0.0f, a1 = 0.0f;
#pragma unroll
            for (int k = 0; k < 15; k++) {
                float w = sdw[ch][k];
                a0 = fmaf(s[k],     w, a0);
                a1 = fmaf(s[k + 1], w, a1);
            }
            *(float2*)&dwv[ch][2 * tp] = make_float2(a0, a1);
        }
    }
    __syncthreads();

    int tl = tid & 63;
    int og = tid >> 6;
    float dreg[24];
#pragma unroll
    for (int ch = 0; ch < 24; ch++) dreg[ch] = dwv[ch][tl];

    int t = t0 + tl;
#pragma unroll
    for (int oo = 0; oo < 8; oo++) {
        int o = og * 8 + oo;
        float a = 0.0f;
#pragma unroll
        for (int c4 = 0; c4 < 6; c4++) {
            float4 w = *(const float4*)&spw[o][c4 * 4];
            a = fmaf(dreg[c4*4+0], w.x, a);
            a = fmaf(dreg[c4*4+1], w.y, a);
            a = fmaf(dreg[c4*4+2], w.z, a);
            a = fmaf(dreg[c4*4+3], w.w, a);
        }
        g_pw[(size_t)o * BT + b * T + t] = a;
    }
}

// ---------------------------------------------------------------------------
// K_scan: phase0 own-slice BN1 partials + device barrier (64 co-resident
// blocks, self-resetting counters) + finalize + prelif + parallel cs/ts
// (8 chunk-warps, tau^32 Horner) + serial m + FC.
// ---------------------------------------------------------------------------
__global__ void __launch_bounds__(256)
k_scan(const float* __restrict__ bn1_g,
       const float* __restrict__ bn1_b,
       const float* __restrict__ tau_geo,
       const float* __restrict__ beta_m,
       const float* __restrict__ alpha,
       const float* __restrict__ gamma_p,
       const float* __restrict__ fcW,
       const float* __restrict__ fcb,
       float* __restrict__ out) {
    extern __shared__ float dsm[];
    float (*sx)[33]   = (float(*)[33])dsm;              // 8448 floats
    float (*svth)[33] = (float(*)[33])(dsm + 8448);     // 8448
    float* Lcs = dsm + 16896;                           // 256
    float* Lts = Lcs + 256;                             // 256
    float* ssc = Lts + 256;                             // 32
    float* ssh = ssc + 32;                              // 32

    int b   = blockIdx.x;
    int tid = threadIdx.x;
    int w   = tid >> 5, lane = tid & 31;

    // Phase 0: BN1 partials over this block's own b-slice (L2/L1 warm-up).
    {
        int o = tid >> 3, p = tid & 7;
        const float4* src = (const float4*)(g_pw + (size_t)o * BT + b * T);
        float s = 0.0f, q = 0.0f;
#pragma unroll 8
        for (int k = 0; k < 32; k++) {
            float4 v = src[p + 8 * k];
            s += v.x + v.y + v.z + v.w;
            q += v.x*v.x + v.y*v.y + v.z*v.z + v.w*v.w;
        }
#pragma unroll
        for (int off = 4; off > 0; off >>= 1) {
            s += __shfl_xor_sync(0xffffffffu, s, off);
            q += __shfl_xor_sync(0xffffffffu, q, off);
        }
        if (p == 0) { g_bps[b * 32 + o] = s; g_bpq[b * 32 + o] = q; }
    }
    __syncthreads();

    // Device barrier: all 64 blocks co-resident (64 <= #SMs). Self-resets.
    if (tid == 0) {
        __threadfence();
        atomicAdd(&g_ctr1, 1);
        while (*((volatile int*)&g_ctr1) < 64) { }
        __threadfence();
        int r = atomicAdd(&g_ctr2, 1);
        if (r == 63) {
            g_ctr2 = 0;
            __threadfence();
            g_ctr1 = 0;
        }
    }
    __syncthreads();

    // BN1 finalize (redundant per block, deterministic fixed order).
    {
        int ch = tid >> 3, p = tid & 7;
        float s = 0.0f, q = 0.0f;
#pragma unroll
        for (int j = 0; j < 8; j++) {
            int bb = p + 8 * j;
            s += g_bps[bb * 32 + ch];
            q += g_bpq[bb * 32 + ch];
        }
#pragma unroll
        for (int off = 4; off > 0; off >>= 1) {
            s += __shfl_xor_sync(0xffffffffu, s, off);
            q += __shfl_xor_sync(0xffffffffu, q, off);
        }
        if (p == 0) {
            float mean = s * (1.0f / BT);
            float var  = fmaxf(q * (1.0f / BT) - mean * mean, 0.0f);
            float sc   = bn1_g[ch] * rsqrtf(var + 1e-5f);
            ssc[ch] = sc;
            ssh[ch] = bn1_b[ch] - mean * sc;
        }
    }
    __syncthreads();

    float tau    = 1.0f / (1.0f + expf(-tau_geo[0]));
    float om_tau = 1.0f - tau;

    // prelif: BN1+ELU+pool4 -> sx[tq][o]
    {
        int o = tid >> 3, p = tid & 7;
        const float4* src = (const float4*)(g_pw + (size_t)o * BT + b * T);
        float sc = ssc[o], shf = ssh[o];
#pragma unroll 8
        for (int k = 0; k < 32; k++) {
            int tq = p + 8 * k;
            float4 v = src[tq];
            float y0 = eluf(fmaf(v.x, sc, shf));
            float y1 = eluf(fmaf(v.y, sc, shf));
            float y2 = eluf(fmaf(v.z, sc, shf));
            float y3 = eluf(fmaf(v.w, sc, shf));
            sx[tq][o] = (y0 + y1 + y2 + y3) * 0.25f;
        }
    }

    // Pass 1: chunk-local cs/ts (zero init). warp w = chunk, lane = o.
    const float* cup = g_curv + (size_t)b * (TQ * 32) + lane;
    const float* tap = g_tang + (size_t)b * (TQ * 32) + lane;
    {
        float cs = 0.0f, ts = 0.0f;
#pragma unroll
        for (int bk = 0; bk < 4; bk++) {
            float cu8[8], ta8[8];
#pragma unroll
            for (int j = 0; j < 8; j++) {
                int t = w * 32 + bk * 8 + j;
                cu8[j] = cup[t * 32];
                ta8[j] = tap[t * 32];
            }
#pragma unroll
            for (int j = 0; j < 8; j++) {
                cs = fmaf(tau, cs, om_tau * cu8[j]);
                ts = fmaf(tau, ts, om_tau * ta8[j]);
            }
        }
        Lcs[w * 32 + lane] = cs;
        Lts[w * 32 + lane] = ts;
    }
    __syncthreads();

    // Pass 2: true init via Horner, recompute, emit vth and x*sens.
    {
        float f32 = tau;
        f32 = f32 * f32; f32 = f32 * f32; f32 = f32 * f32;
        f32 = f32 * f32; f32 = f32 * f32;                     // tau^32

        float Ics = 0.0f, Its = 0.0f;
        for (int j = 0; j < w; j++) {
            Ics = fmaf(Ics, f32, Lcs[j * 32 + lane]);
            Its = fmaf(Its, f32, Lts[j * 32 + lane]);
        }

        float al = alpha[0];
        float gp = gamma_p[0];
        float cs = Ics, ts = Its;
#pragma unroll
        for (int bk = 0; bk < 4; bk++) {
            float cu8[8], ta8[8];
#pragma unroll
            for (int j = 0; j < 8; j++) {
                int t = w * 32 + bk * 8 + j;
                cu8[j] = cup[t * 32];
                ta8[j] = tap[t * 32];
            }
#pragma unroll
            for (int j = 0; j < 8; j++) {
                int t = w * 32 + bk * 8 + j;
                cs = fmaf(tau, cs, om_tau * cu8[j]);
                ts = fmaf(tau, ts, om_tau * ta8[j]);
                svth[t][lane] = fmaxf(fmaf(al, cs, 0.3f), 0.1f);
                float a    = fmaf(-gp, ts, 1.0f);
                float sens = 1.0f / (1.0f + __expf(-a));
                sx[t][lane] *= sens;
            }
        }
    }
    __syncthreads();

    // Serial m-loop (warp 0) + FC.
    if (tid < 32) {
        int o = tid;
        float beta = beta_m[0];
        float m = 0.0f, fr = 0.0f;
#pragma unroll 8
        for (int t = 0; t < TQ; t++) {
            float mn  = fmaf(beta, m, sx[t][o]);
            float dif = mn - svth[t][o];
            bool  sp  = dif > 0.0f;
            m = sp ? dif : mn;
            fr += sp ? 1.0f : 0.0f;
        }
        fr *= (1.0f / (float)TQ);

        float res[4];
#pragma unroll
        for (int k = 0; k < 4; k++) {
            float vv = fr * __ldg(fcW + k * 32 + o);
#pragma unroll
            for (int off = 16; off > 0; off >>= 1)
                vv += __shfl_xor_sync(0xffffffffu, vv, off);
            res[k] = vv;
        }
        if (o == 0) {
#pragma unroll
            for (int k = 0; k < 4; k++)
                out[b * 4 + k] = res[k] + __ldg(fcb + k);
        }
    }
}

// ---------------------------------------------------------------------------
extern "C" void kernel_launch(void* const* d_in, const int* in_sizes, int n_in,
                              void* d_out, int out_size) {
    const float* xb       = (const float*)d_in[0];
    const float* mu       = (const float*)d_in[1];
    const float* sigma    = (const float*)d_in[2];
    const float* curvW    = (const float*)d_in[3];
    const float* tangW    = (const float*)d_in[4];
    const float* spatialW = (const float*)d_in[5];
    const float* bn2_g    = (const float*)d_in[6];
    const float* bn2_b    = (const float*)d_in[7];
    const float* dwW      = (const float*)d_in[8];
    const float* pwW      = (const float*)d_in[9];
    const float* bn1_g    = (const float*)d_in[10];
    const float* bn1_b    = (const float*)d_in[11];
    const float* tau_geo  = (const float*)d_in[12];
    const float* beta_m   = (const float*)d_in[13];
    const float* alpha    = (const float*)d_in[14];
    const float* gamma_p  = (const float*)d_in[15];
    const float* fcW      = (const float*)d_in[16];
    const float* fcb      = (const float*)d_in[17];
    float* out            = (float*)d_out;

    static bool attr_set = false;
    const int scan_smem = (8448 * 2 + 512 + 64) * 4;   // 69888 B
    if (!attr_set) {
        cudaFuncSetAttribute(k_scan, cudaFuncAttributeMaxDynamicSharedMemorySize,
                             scan_smem);
        attr_set = true;
    }

    k_front<<<640, 256>>>(xb, curvW, tangW, mu, sigma, spatialW);
    k_conv<<<1024, 256>>>(dwW, pwW, bn2_g, bn2_b);
    k_scan<<<64, 256, scan_smem>>>(bn1_g, bn1_b, tau_geo, beta_m, alpha,
                                   gamma_p, fcW, fcb, out);
}

// round 15
// speedup vs baseline: 1.0571x; 1.0571x over previous
#include <cuda_runtime.h>
#include <cstdint>

// ---------------------------------------------------------------------------
// GeoEEGSNN forward: B=64, C=64, T=1024, Tq=256. 3 launches:
//   k_front : [0..191] encode (ratio trick, ex2.approx, 4 t/thread)
//             [192..447] curv/tang mapper (pool4 first)   [1 wave, occ4]
//   k_conv  : inline BN2 finalize + BN2+ELU + dw15 + pw(24->32) -> g_pw
//   k_scan  : own-slice BN1 partials + device barrier + finalize +
//             prelif + parallel cs/ts + serial m + FC
// ---------------------------------------------------------------------------

#define B 64
#define CDIM 64
#define T 1024
#define BT (B*T)           // 65536
#define TQ 256
#define NCTA_ENC 64        // partial blocks per feature (one per b)
#define LOG2E 1.4426950408889634f

__device__ float g_s [24 * BT];
__device__ float g_pw[32 * BT];
__device__ float g_curv[B * TQ * 32];   // [b][tq][o]
__device__ float g_tang[B * TQ * 32];
__device__ float g_ep_sum[24 * NCTA_ENC], g_ep_sq[24 * NCTA_ENC];
__device__ float g_bps[B * 32], g_bpq[B * 32];   // per-b BN1 partials
__device__ int   g_ctr1 = 0, g_ctr2 = 0;

// Raw MUFU exp2 (what __expf lowers to after its x*log2e pre-multiply).
__device__ __forceinline__ float fex2(float x) {
    float r;
    asm("ex2.approx.ftz.f32 %0, %1;" : "=f"(r) : "f"(x));
    return r;
}

__device__ __forceinline__ float eluf(float x) {
    return x > 0.0f ? x : (__expf(x) - 1.0f);
}

// ---------------------------------------------------------------------------
// K_front: fat kernel. Blocks [0,192): encode (4 t/thread, one block per
// (f, b)); [192,448): mapper. Shared aliased. occ 4 -> 448 fits one wave.
// ---------------------------------------------------------------------------
__global__ void __launch_bounds__(256, 4)
k_front(const float* __restrict__ xb,
        const float* __restrict__ curvW,
        const float* __restrict__ tangW,
        const float* __restrict__ mu,
        const float* __restrict__ sigma,
        const float* __restrict__ spatialW) {
    __shared__ __align__(16) char smem[16896];

    if (blockIdx.x < 192) {
        // ---------------- encode ----------------
        float4 (*swq)[2]   = (float4(*)[2])smem;             // 2048 B
        float  (*red_s)[8] = (float(*)[8])(smem + 2048);
        float  (*red_q)[8] = (float(*)[8])(smem + 2304);

        int f = blockIdx.x >> 6;          // 0..2
        int b = blockIdx.x & 63;          // 0..63

        float smu[4], sg[4];
#pragma unroll
        for (int p = 0; p < 4; p++) { smu[p] = __ldg(mu + p); sg[p] = __ldg(sigma + p); }
        float d = smu[1] - smu[0];
        bool uni = (fabsf((smu[2] - smu[1]) - d) <= 1e-5f * fmaxf(1.0f, fabsf(d))) &&
                   (fabsf((smu[3] - smu[2]) - d) <= 1e-5f * fmaxf(1.0f, fabsf(d))) &&
                   (fabsf(sg[1] - sg[0]) <= 1e-6f) &&
                   (fabsf(sg[2] - sg[0]) <= 1e-6f) &&
                   (fabsf(sg[3] - sg[0]) <= 1e-6f);
        float q    = -1.0f / (2.0f * sg[0] * sg[0] + 1e-6f);
        float m0   = smu[0];
        float n2qd = -2.0f * q * d;
        float q2    = q * LOG2E;       // fold log2e into the exponent coeffs
        float n2qd2 = n2qd * LOG2E;

        {
            int i = threadIdx.x;         // 256 = 4p x 64c
            int p = i >> 6, c = i & 63;
            int g = f * 4 + p;
            float cp = uni ? expf(q * (float)(p * p) * d * d) : 1.0f;
            float* base = (float*)swq;
            base[c * 8 + p * 2 + 0] = spatialW[(g * 2 + 0) * 64 + c] * cp;
            base[c * 8 + p * 2 + 1] = spatialW[(g * 2 + 1) * 64 + c] * cp;
        }
        __syncthreads();

        int t = threadIdx.x * 4;

        float acc0[8], acc1[8], acc2[8], acc3[8];
#pragma unroll
        for (int i = 0; i < 8; i++) {
            acc0[i] = 0.0f; acc1[i] = 0.0f; acc2[i] = 0.0f; acc3[i] = 0.0f;
        }

        const float* xp = xb + ((size_t)(b * 3 + f) * CDIM) * T + t;

        if (uni) {
#pragma unroll 2
            for (int c = 0; c < CDIM; c++) {
                float4 xv = *(const float4*)(xp + (size_t)c * T);
                float dx0 = xv.x - m0;
                float dx1 = xv.y - m0;
                float dx2 = xv.z - m0;
                float dx3 = xv.w - m0;
                float a0 = fex2(q2 * dx0 * dx0);
                float a1 = fex2(q2 * dx1 * dx1);
                float a2 = fex2(q2 * dx2 * dx2);
                float a3 = fex2(q2 * dx3 * dx3);
                float r0 = fex2(n2qd2 * dx0);
                float r1 = fex2(n2qd2 * dx1);
                float r2 = fex2(n2qd2 * dx2);
                float r3 = fex2(n2qd2 * dx3);
                float4 wA = swq[c][0];
                float4 wB = swq[c][1];
                acc0[0] = fmaf(a0, wA.x, acc0[0]);
                acc0[1] = fmaf(a0, wA.y, acc0[1]);
                acc1[0] = fmaf(a1, wA.x, acc1[0]);
                acc1[1] = fmaf(a1, wA.y, acc1[1]);
                acc2[0] = fmaf(a2, wA.x, acc2[0]);
                acc2[1] = fmaf(a2, wA.y, acc2[1]);
                acc3[0] = fmaf(a3, wA.x, acc3[0]);
                acc3[1] = fmaf(a3, wA.y, acc3[1]);
                a0 *= r0; a1 *= r1; a2 *= r2; a3 *= r3;
                acc0[2] = fmaf(a0, wA.z, acc0[2]);
                acc0[3] = fmaf(a0, wA.w, acc0[3]);
                acc1[2] = fmaf(a1, wA.z, acc1[2]);
                acc1[3] = fmaf(a1, wA.w, acc1[3]);
                acc2[2] = fmaf(a2, wA.z, acc2[2]);
                acc2[3] = fmaf(a2, wA.w, acc2[3]);
                acc3[2] = fmaf(a3, wA.z, acc3[2]);
                acc3[3] = fmaf(a3, wA.w, acc3[3]);
                a0 *= r0; a1 *= r1; a2 *= r2; a3 *= r3;
                acc0[4] = fmaf(a0, wB.x, acc0[4]);
                acc0[5] = fmaf(a0, wB.y, acc0[5]);
                acc1[4] = fmaf(a1, wB.x, acc1[4]);
                acc1[5] = fmaf(a1, wB.y, acc1[5]);
                acc2[4] = fmaf(a2, wB.x, acc2[4]);
                acc2[5] = fmaf(a2, wB.y, acc2[5]);
                acc3[4] = fmaf(a3, wB.x, acc3[4]);
                acc3[5] = fmaf(a3, wB.y, acc3[5]);
                a0 *= r0; a1 *= r1; a2 *= r2; a3 *= r3;
                acc0[6] = fmaf(a0, wB.z, acc0[6]);
                acc0[7] = fmaf(a0, wB.w, acc0[7]);
                acc1[6] = fmaf(a1, wB.z, acc1[6]);
                acc1[7] = fmaf(a1, wB.w, acc1[7]);
                acc2[6] = fmaf(a2, wB.z, acc2[6]);
                acc2[7] = fmaf(a2, wB.w, acc2[7]);
                acc3[6] = fmaf(a3, wB.z, acc3[6]);
                acc3[7] = fmaf(a3, wB.w, acc3[7]);
            }
        } else {
            float sneg[4];
#pragma unroll
            for (int p = 0; p < 4; p++) sneg[p] = -1.0f / (2.0f * sg[p] * sg[p] + 1e-6f);
#pragma unroll 2
            for (int c = 0; c < CDIM; c++) {
                float4 xv = *(const float4*)(xp + (size_t)c * T);
                float4 wA = swq[c][0];
                float4 wB = swq[c][1];
                float wx[4] = {wA.x, wA.z, wB.x, wB.z};
                float wy[4] = {wA.y, wA.w, wB.y, wB.w};
#pragma unroll
                for (int p = 0; p < 4; p++) {
                    float dx0 = xv.x - smu[p];
                    float dx1 = xv.y - smu[p];
                    float dx2 = xv.z - smu[p];
                    float dx3 = xv.w - smu[p];
                    float e0 = expf(dx0 * dx0 * sneg[p]);
                    float e1 = expf(dx1 * dx1 * sneg[p]);
                    float e2 = expf(dx2 * dx2 * sneg[p]);
                    float e3 = expf(dx3 * dx3 * sneg[p]);
                    acc0[p*2+0] = fmaf(e0, wx[p], acc0[p*2+0]);
                    acc0[p*2+1] = fmaf(e0, wy[p], acc0[p*2+1]);
                    acc1[p*2+0] = fmaf(e1, wx[p], acc1[p*2+0]);
                    acc1[p*2+1] = fmaf(e1, wy[p], acc1[p*2+1]);
                    acc2[p*2+0] = fmaf(e2, wx[p], acc2[p*2+0]);
                    acc2[p*2+1] = fmaf(e2, wy[p], acc2[p*2+1]);
                    acc3[p*2+0] = fmaf(e3, wx[p], acc3[p*2+0]);
                    acc3[p*2+1] = fmaf(e3, wy[p], acc3[p*2+1]);
                }
            }
        }

#pragma unroll
        for (int cc = 0; cc < 8; cc++)
            *(float4*)(g_s + (size_t)(f * 8 + cc) * BT + b * T + t) =
                make_float4(acc0[cc], acc1[cc], acc2[cc], acc3[cc]);

        int w = threadIdx.x >> 5, lane = threadIdx.x & 31;
#pragma unroll
        for (int cc = 0; cc < 8; cc++) {
            float s  = (acc0[cc] + acc1[cc]) + (acc2[cc] + acc3[cc]);
            float qv = (acc0[cc] * acc0[cc] + acc1[cc] * acc1[cc]) +
                       (acc2[cc] * acc2[cc] + acc3[cc] * acc3[cc]);
#pragma unroll
            for (int off = 16; off > 0; off >>= 1) {
                s  += __shfl_xor_sync(0xffffffffu, s, off);
                qv += __shfl_xor_sync(0xffffffffu, qv, off);
            }
            if (lane == 0) { red_s[w][cc] = s; red_q[w][cc] = qv; }
        }
        __syncthreads();
        if (threadIdx.x < 8) {
            float S = 0.0f, Q = 0.0f;
#pragma unroll
            for (int ww = 0; ww < 8; ww++) { S += red_s[ww][threadIdx.x]; Q += red_q[ww][threadIdx.x]; }
            g_ep_sum[(f * 8 + threadIdx.x) * NCTA_ENC + b] = S;
            g_ep_sq [(f * 8 + threadIdx.x) * NCTA_ENC + b] = Q;
        }
    } else {
        // ---------------- mapper ----------------
        float (*wT)[64][32] = (float(*)[64][32])smem;   // 16KB

        int mbid = blockIdx.x - 192;
        for (int i = threadIdx.x; i < 2048; i += 256) {
            int o = i >> 6, c = i & 63;
            wT[0][c][o] = curvW[i];
            wT[1][c][o] = tangW[i];
        }
        __syncthreads();

        int b    = mbid >> 2;
        int tq   = (mbid & 3) * 64 + (threadIdx.x & 63);
        int sub  = threadIdx.x >> 6;
        int feat = sub >> 1;
        int ob   = (sub & 1) * 16;

        float a[16];
#pragma unroll
        for (int j = 0; j < 16; j++) a[j] = 0.0f;

        const float* x = xb + ((size_t)(b * 3 + 1 + feat) * CDIM) * T + tq * 4;

#pragma unroll 4
        for (int c = 0; c < CDIM; c++) {
            float4 v = *(const float4*)(x + (size_t)c * T);
            float p = (v.x + v.y + v.z + v.w) * 0.25f;
#pragma unroll
            for (int j4 = 0; j4 < 4; j4++) {
                float4 w = *(const float4*)&wT[feat][c][ob + j4 * 4];
                a[j4*4+0] = fmaf(p, w.x, a[j4*4+0]);
                a[j4*4+1] = fmaf(p, w.y, a[j4*4+1]);
                a[j4*4+2] = fmaf(p, w.z, a[j4*4+2]);
                a[j4*4+3] = fmaf(p, w.w, a[j4*4+3]);
            }
        }

        float* dst = (feat == 0 ? g_curv : g_tang) +
                     (size_t)b * (TQ * 32) + (size_t)tq * 32 + ob;
#pragma unroll
        for (int j4 = 0; j4 < 4; j4++)
            *(float4*)(dst + j4 * 4) =
                make_float4(a[j4*4+0], a[j4*4+1], a[j4*4+2], a[j4*4+3]);
    }
}

// ---------------------------------------------------------------------------
// K_conv: inline BN2 finalize (64 partials/ch) + BN2+ELU + dw15 + pw(24->32).
// No min-blocks clause: 48 regs natural, no spills.
// ---------------------------------------------------------------------------
__global__ void __launch_bounds__(256)
k_conv(const float* __restrict__ dwW,
       const float* __restrict__ pwW,
       const float* __restrict__ bn2_g,
       const float* __restrict__ bn2_b) {
    __shared__ float sh[24][80];
    __shared__ float sdw[24][16];
    __shared__ float spw[32][24];
    __shared__ float dwv[24][68];
    __shared__ float ssc2[24], ssh2[24];

    int b   = blockIdx.x >> 4;
    int t0  = (blockIdx.x & 15) * 64;
    int tid = threadIdx.x;
    int wid = tid >> 5, lane = tid & 31;

    for (int i = tid; i < 360; i += 256) sdw[i / 15][i % 15] = dwW[i];
    for (int i = tid; i < 768; i += 256) spw[i / 24][i % 24] = pwW[i];

#pragma unroll
    for (int cc = 0; cc < 3; cc++) {
        int ch = wid * 3 + cc;
        const float* ps = g_ep_sum + ch * NCTA_ENC;
        const float* pq = g_ep_sq  + ch * NCTA_ENC;
        float s  = ps[lane] + ps[lane + 32];
        float qv = pq[lane] + pq[lane + 32];
#pragma unroll
        for (int off = 16; off > 0; off >>= 1) {
            s  += __shfl_xor_sync(0xffffffffu, s, off);
            qv += __shfl_xor_sync(0xffffffffu, qv, off);
        }
        if (lane == 0) {
            float mean = s * (1.0f / BT);
            float var  = fmaxf(qv * (1.0f / BT) - mean * mean, 0.0f);
            float sc   = __ldg(bn2_g + ch) * rsqrtf(var + 1e-5f);
            ssc2[ch] = sc;
            ssh2[ch] = __ldg(bn2_b + ch) - mean * sc;
        }
    }
    __syncthreads();

    for (int i = tid; i < 24 * 78; i += 256) {
        int ch = i / 78, j = i % 78;
        int t = t0 + j - 7;
        float v = 0.0f;
        if (t >= 0 && t < T) {
            float raw = g_s[(size_t)ch * BT + b * T + t];
            v = eluf(fmaf(raw, ssc2[ch], ssh2[ch]));
        }
        sh[ch][j] = v;
    }
    __syncthreads();

    {
        int tp = tid & 31;
        int cg = tid >> 5;
#pragma unroll
        for (int cc = 0; cc < 3; cc++) {
            int ch = cg * 3 + cc;
            float s[18];
#pragma unroll
            for (int j = 0; j < 9; j++) {
                float2 v = *(const float2*)&sh[ch][2 * tp + 2 * j];
                s[2*j] = v.x; s[2*j+1] = v.y;
            }
            float a0 = 0.0f, a1 = 0.0f;
#pragma unroll
            for (int k = 0; k < 15; k++) {
                float w = sdw[ch][k];
                a0 = fmaf(s[k],     w, a0);
                a1 = fmaf(s[k + 1], w, a1);
            }
            *(float2*)&dwv[ch][2 * tp] = make_float2(a0, a1);
        }
    }
    __syncthreads();

    int tl = tid & 63;
    int og = tid >> 6;
    float dreg[24];
#pragma unroll
    for (int ch = 0; ch < 24; ch++) dreg[ch] = dwv[ch][tl];

    int t = t0 + tl;
#pragma unroll
    for (int oo = 0; oo < 8; oo++) {
        int o = og * 8 + oo;
        float a = 0.0f;
#pragma unroll
        for (int c4 = 0; c4 < 6; c4++) {
            float4 w = *(const float4*)&spw[o][c4 * 4];
            a = fmaf(dreg[c4*4+0], w.x, a);
            a = fmaf(dreg[c4*4+1], w.y, a);
            a = fmaf(dreg[c4*4+2], w.z, a);
            a = fmaf(dreg[c4*4+3], w.w, a);
        }
        g_pw[(size_t)o * BT + b * T + t] = a;
    }
}

// ---------------------------------------------------------------------------
// K_scan: phase0 own-slice BN1 partials + device barrier (64 co-resident
// blocks, self-resetting counters) + finalize + prelif + parallel cs/ts
// (8 chunk-warps, tau^32 Horner) + serial m + FC.
// ---------------------------------------------------------------------------
__global__ void __launch_bounds__(256)
k_scan(const float* __restrict__ bn1_g,
       const float* __restrict__ bn1_b,
       const float* __restrict__ tau_geo,
       const float* __restrict__ beta_m,
       const float* __restrict__ alpha,
       const float* __restrict__ gamma_p,
       const float* __restrict__ fcW,
       const float* __restrict__ fcb,
       float* __restrict__ out) {
    extern __shared__ float dsm[];
    float (*sx)[33]   = (float(*)[33])dsm;              // 8448 floats
    float (*svth)[33] = (float(*)[33])(dsm + 8448);     // 8448
    float* Lcs = dsm + 16896;                           // 256
    float* Lts = Lcs + 256;                             // 256
    float* ssc = Lts + 256;                             // 32
    float* ssh = ssc + 32;                              // 32

    int b   = blockIdx.x;
    int tid = threadIdx.x;
    int w   = tid >> 5, lane = tid & 31;

    // Phase 0: BN1 partials over this block's own b-slice (L2/L1 warm-up).
    {
        int o = tid >> 3, p = tid & 7;
        const float4* src = (const float4*)(g_pw + (size_t)o * BT + b * T);
        float s = 0.0f, q = 0.0f;
#pragma unroll 8
        for (int k = 0; k < 32; k++) {
            float4 v = src[p + 8 * k];
            s += v.x + v.y + v.z + v.w;
            q += v.x*v.x + v.y*v.y + v.z*v.z + v.w*v.w;
        }
#pragma unroll
        for (int off = 4; off > 0; off >>= 1) {
            s += __shfl_xor_sync(0xffffffffu, s, off);
            q += __shfl_xor_sync(0xffffffffu, q, off);
        }
        if (p == 0) { g_bps[b * 32 + o] = s; g_bpq[b * 32 + o] = q; }
    }
    __syncthreads();

    // Device barrier: all 64 blocks co-resident (64 <= #SMs). Self-resets.
    if (tid == 0) {
        __threadfence();
        atomicAdd(&g_ctr1, 1);
        while (*((volatile int*)&g_ctr1) < 64) { }
        __threadfence();
        int r = atomicAdd(&g_ctr2, 1);
        if (r == 63) {
            g_ctr2 = 0;
            __threadfence();
            g_ctr1 = 0;
        }
    }
    __syncthreads();

    // BN1 finalize (redundant per block, deterministic fixed order).
    {
        int ch = tid >> 3, p = tid & 7;
        float s = 0.0f, q = 0.0f;
#pragma unroll
        for (int j = 0; j < 8; j++) {
            int bb = p + 8 * j;
            s += g_bps[bb * 32 + ch];
            q += g_bpq[bb * 32 + ch];
        }
#pragma unroll
        for (int off = 4; off > 0; off >>= 1) {
            s += __shfl_xor_sync(0xffffffffu, s, off);
            q += __shfl_xor_sync(0xffffffffu, q, off);
        }
        if (p == 0) {
            float mean = s * (1.0f / BT);
            float var  = fmaxf(q * (1.0f / BT) - mean * mean, 0.0f);
            float sc   = bn1_g[ch] * rsqrtf(var + 1e-5f);
            ssc[ch] = sc;
            ssh[ch] = bn1_b[ch] - mean * sc;
        }
    }
    __syncthreads();

    float tau    = 1.0f / (1.0f + expf(-tau_geo[0]));
    float om_tau = 1.0f - tau;

    // prelif: BN1+ELU+pool4 -> sx[tq][o]
    {
        int o = tid >> 3, p = tid & 7;
        const float4* src = (const float4*)(g_pw + (size_t)o * BT + b * T);
        float sc = ssc[o], shf = ssh[o];
#pragma unroll 8
        for (int k = 0; k < 32; k++) {
            int tq = p + 8 * k;
            float4 v = src[tq];
            float y0 = eluf(fmaf(v.x, sc, shf));
            float y1 = eluf(fmaf(v.y, sc, shf));
            float y2 = eluf(fmaf(v.z, sc, shf));
            float y3 = eluf(fmaf(v.w, sc, shf));
            sx[tq][o] = (y0 + y1 + y2 + y3) * 0.25f;
        }
    }

    // Pass 1: chunk-local cs/ts (zero init). warp w = chunk, lane = o.
    const float* cup = g_curv + (size_t)b * (TQ * 32) + lane;
    const float* tap = g_tang + (size_t)b * (TQ * 32) + lane;
    {
        float cs = 0.0f, ts = 0.0f;
#pragma unroll
        for (int bk = 0; bk < 4; bk++) {
            float cu8[8], ta8[8];
#pragma unroll
            for (int j = 0; j < 8; j++) {
                int t = w * 32 + bk * 8 + j;
                cu8[j] = cup[t * 32];
                ta8[j] = tap[t * 32];
            }
#pragma unroll
            for (int j = 0; j < 8; j++) {
                cs = fmaf(tau, cs, om_tau * cu8[j]);
                ts = fmaf(tau, ts, om_tau * ta8[j]);
            }
        }
        Lcs[w * 32 + lane] = cs;
        Lts[w * 32 + lane] = ts;
    }
    __syncthreads();

    // Pass 2: true init via Horner, recompute, emit vth and x*sens.
    {
        float f32 = tau;
        f32 = f32 * f32; f32 = f32 * f32; f32 = f32 * f32;
        f32 = f32 * f32; f32 = f32 * f32;                     // tau^32

        float Ics = 0.0f, Its = 0.0f;
        for (int j = 0; j < w; j++) {
            Ics = fmaf(Ics, f32, Lcs[j * 32 + lane]);
            Its = fmaf(Its, f32, Lts[j * 32 + lane]);
        }

        float al = alpha[0];
        float gp = gamma_p[0];
        float cs = Ics, ts = Its;
#pragma unroll
        for (int bk = 0; bk < 4; bk++) {
            float cu8[8], ta8[8];
#pragma unroll
            for (int j = 0; j < 8; j++) {
                int t = w * 32 + bk * 8 + j;
                cu8[j] = cup[t * 32];
                ta8[j] = tap[t * 32];
            }
#pragma unroll
            for (int j = 0; j < 8; j++) {
                int t = w * 32 + bk * 8 + j;
                cs = fmaf(tau, cs, om_tau * cu8[j]);
                ts = fmaf(tau, ts, om_tau * ta8[j]);
                svth[t][lane] = fmaxf(fmaf(al, cs, 0.3f), 0.1f);
                float a    = fmaf(-gp, ts, 1.0f);
                float sens = 1.0f / (1.0f + __expf(-a));
                sx[t][lane] *= sens;
            }
        }
    }
    __syncthreads();

    // Serial m-loop (warp 0) + FC.
    if (tid < 32) {
        int o = tid;
        float beta = beta_m[0];
        float m = 0.0f, fr = 0.0f;
#pragma unroll 8
        for (int t = 0; t < TQ; t++) {
            float mn  = fmaf(beta, m, sx[t][o]);
            float dif = mn - svth[t][o];
            bool  sp  = dif > 0.0f;
            m = sp ? dif : mn;
            fr += sp ? 1.0f : 0.0f;
        }
        fr *= (1.0f / (float)TQ);

        float res[4];
#pragma unroll
        for (int k = 0; k < 4; k++) {
            float vv = fr * __ldg(fcW + k * 32 + o);
#pragma unroll
            for (int off = 16; off > 0; off >>= 1)
                vv += __shfl_xor_sync(0xffffffffu, vv, off);
            res[k] = vv;
        }
        if (o == 0) {
#pragma unroll
            for (int k = 0; k < 4; k++)
                out[b * 4 + k] = res[k] + __ldg(fcb + k);
        }
    }
}

// ---------------------------------------------------------------------------
extern "C" void kernel_launch(void* const* d_in, const int* in_sizes, int n_in,
                              void* d_out, int out_size) {
    const float* xb       = (const float*)d_in[0];
    const float* mu       = (const float*)d_in[1];
    const float* sigma    = (const float*)d_in[2];
    const float* curvW    = (const float*)d_in[3];
    const float* tangW    = (const float*)d_in[4];
    const float* spatialW = (const float*)d_in[5];
    const float* bn2_g    = (const float*)d_in[6];
    const float* bn2_b    = (const float*)d_in[7];
    const float* dwW      = (const float*)d_in[8];
    const float* pwW      = (const float*)d_in[9];
    const float* bn1_g    = (const float*)d_in[10];
    const float* bn1_b    = (const float*)d_in[11];
    const float* tau_geo  = (const float*)d_in[12];
    const float* beta_m   = (const float*)d_in[13];
    const float* alpha    = (const float*)d_in[14];
    const float* gamma_p  = (const float*)d_in[15];
    const float* fcW      = (const float*)d_in[16];
    const float* fcb      = (const float*)d_in[17];
    float* out            = (float*)d_out;

    static bool attr_set = false;
    const int scan_smem = (8448 * 2 + 512 + 64) * 4;   // 69888 B
    if (!attr_set) {
        cudaFuncSetAttribute(k_scan, cudaFuncAttributeMaxDynamicSharedMemorySize,
                             scan_smem);
        attr_set = true;
    }

    k_front<<<448, 256>>>(xb, curvW, tangW, mu, sigma, spatialW);
    k_conv<<<1024, 256>>>(dwW, pwW, bn2_g, bn2_b);
    k_scan<<<64, 256, scan_smem>>>(bn1_g, bn1_b, tau_geo, beta_m, alpha,
                                   gamma_p, fcW, fcb, out);
}

// round 16
// speedup vs baseline: 1.0635x; 1.0060x over previous
#include <cuda_runtime.h>
#include <cstdint>

// ---------------------------------------------------------------------------
// GeoEEGSNN forward: B=64, C=64, T=1024, Tq=256. 3 launches:
//   k_front : [0..191] encode (ratio trick, ex2.approx, 4 t/thread)
//             [192..447] curv/tang mapper (pool4 first)   [1 wave, occ4]
//   k_conv  : inline BN2 finalize + BN2+ELU + dw15 + pw(24->32), 128-t tiles
//   k_scan  : own-slice BN1 partials + device barrier + finalize +
//             prelif + parallel cs/ts + serial m + FC
// ---------------------------------------------------------------------------

#define B 64
#define CDIM 64
#define T 1024
#define BT (B*T)           // 65536
#define TQ 256
#define NCTA_ENC 64        // partial blocks per feature (one per b)
#define LOG2E 1.4426950408889634f

__device__ float g_s [24 * BT];
__device__ float g_pw[32 * BT];
__device__ float g_curv[B * TQ * 32];   // [b][tq][o]
__device__ float g_tang[B * TQ * 32];
__device__ float g_ep_sum[24 * NCTA_ENC], g_ep_sq[24 * NCTA_ENC];
__device__ float g_bps[B * 32], g_bpq[B * 32];   // per-b BN1 partials
__device__ int   g_ctr1 = 0, g_ctr2 = 0;

// Raw MUFU exp2 (what __expf lowers to after its x*log2e pre-multiply).
__device__ __forceinline__ float fex2(float x) {
    float r;
    asm("ex2.approx.ftz.f32 %0, %1;" : "=f"(r) : "f"(x));
    return r;
}

__device__ __forceinline__ float eluf(float x) {
    return x > 0.0f ? x : (__expf(x) - 1.0f);
}

// ---------------------------------------------------------------------------
// K_front: fat kernel. Blocks [0,192): encode (4 t/thread, one block per
// (f, b)); [192,448): mapper. Shared aliased. occ 4 -> 448 fits one wave.
// ---------------------------------------------------------------------------
__global__ void __launch_bounds__(256, 4)
k_front(const float* __restrict__ xb,
        const float* __restrict__ curvW,
        const float* __restrict__ tangW,
        const float* __restrict__ mu,
        const float* __restrict__ sigma,
        const float* __restrict__ spatialW) {
    __shared__ __align__(16) char smem[16896];

    if (blockIdx.x < 192) {
        // ---------------- encode ----------------
        float4 (*swq)[2]   = (float4(*)[2])smem;             // 2048 B
        float  (*red_s)[8] = (float(*)[8])(smem + 2048);
        float  (*red_q)[8] = (float(*)[8])(smem + 2304);

        int f = blockIdx.x >> 6;          // 0..2
        int b = blockIdx.x & 63;          // 0..63

        float smu[4], sg[4];
#pragma unroll
        for (int p = 0; p < 4; p++) { smu[p] = __ldg(mu + p); sg[p] = __ldg(sigma + p); }
        float d = smu[1] - smu[0];
        bool uni = (fabsf((smu[2] - smu[1]) - d) <= 1e-5f * fmaxf(1.0f, fabsf(d))) &&
                   (fabsf((smu[3] - smu[2]) - d) <= 1e-5f * fmaxf(1.0f, fabsf(d))) &&
                   (fabsf(sg[1] - sg[0]) <= 1e-6f) &&
                   (fabsf(sg[2] - sg[0]) <= 1e-6f) &&
                   (fabsf(sg[3] - sg[0]) <= 1e-6f);
        float q    = -1.0f / (2.0f * sg[0] * sg[0] + 1e-6f);
        float m0   = smu[0];
        float n2qd = -2.0f * q * d;
        float q2    = q * LOG2E;
        float n2qd2 = n2qd * LOG2E;

        {
            int i = threadIdx.x;         // 256 = 4p x 64c
            int p = i >> 6, c = i & 63;
            int g = f * 4 + p;
            float cp = uni ? expf(q * (float)(p * p) * d * d) : 1.0f;
            float* base = (float*)swq;
            base[c * 8 + p * 2 + 0] = spatialW[(g * 2 + 0) * 64 + c] * cp;
            base[c * 8 + p * 2 + 1] = spatialW[(g * 2 + 1) * 64 + c] * cp;
        }
        __syncthreads();

        int t = threadIdx.x * 4;

        float acc0[8], acc1[8], acc2[8], acc3[8];
#pragma unroll
        for (int i = 0; i < 8; i++) {
            acc0[i] = 0.0f; acc1[i] = 0.0f; acc2[i] = 0.0f; acc3[i] = 0.0f;
        }

        const float* xp = xb + ((size_t)(b * 3 + f) * CDIM) * T + t;

        if (uni) {
#pragma unroll 2
            for (int c = 0; c < CDIM; c++) {
                float4 xv = *(const float4*)(xp + (size_t)c * T);
                float dx0 = xv.x - m0;
                float dx1 = xv.y - m0;
                float dx2 = xv.z - m0;
                float dx3 = xv.w - m0;
                float a0 = fex2(q2 * dx0 * dx0);
                float a1 = fex2(q2 * dx1 * dx1);
                float a2 = fex2(q2 * dx2 * dx2);
                float a3 = fex2(q2 * dx3 * dx3);
                float r0 = fex2(n2qd2 * dx0);
                float r1 = fex2(n2qd2 * dx1);
                float r2 = fex2(n2qd2 * dx2);
                float r3 = fex2(n2qd2 * dx3);
                float4 wA = swq[c][0];
                float4 wB = swq[c][1];
                acc0[0] = fmaf(a0, wA.x, acc0[0]);
                acc0[1] = fmaf(a0, wA.y, acc0[1]);
                acc1[0] = fmaf(a1, wA.x, acc1[0]);
                acc1[1] = fmaf(a1, wA.y, acc1[1]);
                acc2[0] = fmaf(a2, wA.x, acc2[0]);
                acc2[1] = fmaf(a2, wA.y, acc2[1]);
                acc3[0] = fmaf(a3, wA.x, acc3[0]);
                acc3[1] = fmaf(a3, wA.y, acc3[1]);
                a0 *= r0; a1 *= r1; a2 *= r2; a3 *= r3;
                acc0[2] = fmaf(a0, wA.z, acc0[2]);
                acc0[3] = fmaf(a0, wA.w, acc0[3]);
                acc1[2] = fmaf(a1, wA.z, acc1[2]);
                acc1[3] = fmaf(a1, wA.w, acc1[3]);
                acc2[2] = fmaf(a2, wA.z, acc2[2]);
                acc2[3] = fmaf(a2, wA.w, acc2[3]);
                acc3[2] = fmaf(a3, wA.z, acc3[2]);
                acc3[3] = fmaf(a3, wA.w, acc3[3]);
                a0 *= r0; a1 *= r1; a2 *= r2; a3 *= r3;
                acc0[4] = fmaf(a0, wB.x, acc0[4]);
                acc0[5] = fmaf(a0, wB.y, acc0[5]);
                acc1[4] = fmaf(a1, wB.x, acc1[4]);
                acc1[5] = fmaf(a1, wB.y, acc1[5]);
                acc2[4] = fmaf(a2, wB.x, acc2[4]);
                acc2[5] = fmaf(a2, wB.y, acc2[5]);
                acc3[4] = fmaf(a3, wB.x, acc3[4]);
                acc3[5] = fmaf(a3, wB.y, acc3[5]);
                a0 *= r0; a1 *= r1; a2 *= r2; a3 *= r3;
                acc0[6] = fmaf(a0, wB.z, acc0[6]);
                acc0[7] = fmaf(a0, wB.w, acc0[7]);
                acc1[6] = fmaf(a1, wB.z, acc1[6]);
                acc1[7] = fmaf(a1, wB.w, acc1[7]);
                acc2[6] = fmaf(a2, wB.z, acc2[6]);
                acc2[7] = fmaf(a2, wB.w, acc2[7]);
                acc3[6] = fmaf(a3, wB.z, acc3[6]);
                acc3[7] = fmaf(a3, wB.w, acc3[7]);
            }
        } else {
            float sneg[4];
#pragma unroll
            for (int p = 0; p < 4; p++) sneg[p] = -1.0f / (2.0f * sg[p] * sg[p] + 1e-6f);
#pragma unroll 2
            for (int c = 0; c < CDIM; c++) {
                float4 xv = *(const float4*)(xp + (size_t)c * T);
                float4 wA = swq[c][0];
                float4 wB = swq[c][1];
                float wx[4] = {wA.x, wA.z, wB.x, wB.z};
                float wy[4] = {wA.y, wA.w, wB.y, wB.w};
#pragma unroll
                for (int p = 0; p < 4; p++) {
                    float dx0 = xv.x - smu[p];
                    float dx1 = xv.y - smu[p];
                    float dx2 = xv.z - smu[p];
                    float dx3 = xv.w - smu[p];
                    float e0 = expf(dx0 * dx0 * sneg[p]);
                    float e1 = expf(dx1 * dx1 * sneg[p]);
                    float e2 = expf(dx2 * dx2 * sneg[p]);
                    float e3 = expf(dx3 * dx3 * sneg[p]);
                    acc0[p*2+0] = fmaf(e0, wx[p], acc0[p*2+0]);
                    acc0[p*2+1] = fmaf(e0, wy[p], acc0[p*2+1]);
                    acc1[p*2+0] = fmaf(e1, wx[p], acc1[p*2+0]);
                    acc1[p*2+1] = fmaf(e1, wy[p], acc1[p*2+1]);
                    acc2[p*2+0] = fmaf(e2, wx[p], acc2[p*2+0]);
                    acc2[p*2+1] = fmaf(e2, wy[p], acc2[p*2+1]);
                    acc3[p*2+0] = fmaf(e3, wx[p], acc3[p*2+0]);
                    acc3[p*2+1] = fmaf(e3, wy[p], acc3[p*2+1]);
                }
            }
        }

#pragma unroll
        for (int cc = 0; cc < 8; cc++)
            *(float4*)(g_s + (size_t)(f * 8 + cc) * BT + b * T + t) =
                make_float4(acc0[cc], acc1[cc], acc2[cc], acc3[cc]);

        int w = threadIdx.x >> 5, lane = threadIdx.x & 31;
#pragma unroll
        for (int cc = 0; cc < 8; cc++) {
            float s  = (acc0[cc] + acc1[cc]) + (acc2[cc] + acc3[cc]);
            float qv = (acc0[cc] * acc0[cc] + acc1[cc] * acc1[cc]) +
                       (acc2[cc] * acc2[cc] + acc3[cc] * acc3[cc]);
#pragma unroll
            for (int off = 16; off > 0; off >>= 1) {
                s  += __shfl_xor_sync(0xffffffffu, s, off);
                qv += __shfl_xor_sync(0xffffffffu, qv, off);
            }
            if (lane == 0) { red_s[w][cc] = s; red_q[w][cc] = qv; }
        }
        __syncthreads();
        if (threadIdx.x < 8) {
            float S = 0.0f, Q = 0.0f;
#pragma unroll
            for (int ww = 0; ww < 8; ww++) { S += red_s[ww][threadIdx.x]; Q += red_q[ww][threadIdx.x]; }
            g_ep_sum[(f * 8 + threadIdx.x) * NCTA_ENC + b] = S;
            g_ep_sq [(f * 8 + threadIdx.x) * NCTA_ENC + b] = Q;
        }
    } else {
        // ---------------- mapper ----------------
        float (*wT)[64][32] = (float(*)[64][32])smem;   // 16KB

        int mbid = blockIdx.x - 192;
        for (int i = threadIdx.x; i < 2048; i += 256) {
            int o = i >> 6, c = i & 63;
            wT[0][c][o] = curvW[i];
            wT[1][c][o] = tangW[i];
        }
        __syncthreads();

        int b    = mbid >> 2;
        int tq   = (mbid & 3) * 64 + (threadIdx.x & 63);
        int sub  = threadIdx.x >> 6;
        int feat = sub >> 1;
        int ob   = (sub & 1) * 16;

        float a[16];
#pragma unroll
        for (int j = 0; j < 16; j++) a[j] = 0.0f;

        const float* x = xb + ((size_t)(b * 3 + 1 + feat) * CDIM) * T + tq * 4;

#pragma unroll 4
        for (int c = 0; c < CDIM; c++) {
            float4 v = *(const float4*)(x + (size_t)c * T);
            float p = (v.x + v.y + v.z + v.w) * 0.25f;
#pragma unroll
            for (int j4 = 0; j4 < 4; j4++) {
                float4 w = *(const float4*)&wT[feat][c][ob + j4 * 4];
                a[j4*4+0] = fmaf(p, w.x, a[j4*4+0]);
                a[j4*4+1] = fmaf(p, w.y, a[j4*4+1]);
                a[j4*4+2] = fmaf(p, w.z, a[j4*4+2]);
                a[j4*4+3] = fmaf(p, w.w, a[j4*4+3]);
            }
        }

        float* dst = (feat == 0 ? g_curv : g_tang) +
                     (size_t)b * (TQ * 32) + (size_t)tq * 32 + ob;
#pragma unroll
        for (int j4 = 0; j4 < 4; j4++)
            *(float4*)(dst + j4 * 4) =
                make_float4(a[j4*4+0], a[j4*4+1], a[j4*4+2], a[j4*4+3]);
    }
}

// ---------------------------------------------------------------------------
// K_conv: inline BN2 finalize + BN2+ELU + dw15 + pw(24->32).
// 128-t tiles, 512 blocks (halved per-block fixed cost, halo 22%->11%).
// dw: 64 t-pairs x 4 ch-groups(6). pw: 128 t x 2 o-groups(16).
// ---------------------------------------------------------------------------
__global__ void __launch_bounds__(256)
k_conv(const float* __restrict__ dwW,
       const float* __restrict__ pwW,
       const float* __restrict__ bn2_g,
       const float* __restrict__ bn2_b) {
    __shared__ float sh[24][144];        // 142 used (128 + 14 halo)
    __shared__ float sdw[24][16];
    __shared__ float spw[32][24];
    __shared__ float dwv[24][132];       // 128 used
    __shared__ float ssc2[24], ssh2[24];

    int b   = blockIdx.x >> 3;
    int t0  = (blockIdx.x & 7) * 128;
    int tid = threadIdx.x;
    int wid = tid >> 5, lane = tid & 31;

    for (int i = tid; i < 360; i += 256) sdw[i / 15][i % 15] = dwW[i];
    for (int i = tid; i < 768; i += 256) spw[i / 24][i % 24] = pwW[i];

#pragma unroll
    for (int cc = 0; cc < 3; cc++) {
        int ch = wid * 3 + cc;
        const float* ps = g_ep_sum + ch * NCTA_ENC;
        const float* pq = g_ep_sq  + ch * NCTA_ENC;
        float s  = ps[lane] + ps[lane + 32];
        float qv = pq[lane] + pq[lane + 32];
#pragma unroll
        for (int off = 16; off > 0; off >>= 1) {
            s  += __shfl_xor_sync(0xffffffffu, s, off);
            qv += __shfl_xor_sync(0xffffffffu, qv, off);
        }
        if (lane == 0) {
            float mean = s * (1.0f / BT);
            float var  = fmaxf(qv * (1.0f / BT) - mean * mean, 0.0f);
            float sc   = __ldg(bn2_g + ch) * rsqrtf(var + 1e-5f);
            ssc2[ch] = sc;
            ssh2[ch] = __ldg(bn2_b + ch) - mean * sc;
        }
    }
    __syncthreads();

    for (int i = tid; i < 24 * 142; i += 256) {
        int ch = i / 142, j = i % 142;
        int t = t0 + j - 7;
        float v = 0.0f;
        if (t >= 0 && t < T) {
            float raw = g_s[(size_t)ch * BT + b * T + t];
            v = eluf(fmaf(raw, ssc2[ch], ssh2[ch]));
        }
        sh[ch][j] = v;
    }
    __syncthreads();

    // depthwise: thread = (t-pair tp 0..63, ch-group cg 0..3 of 6 ch)
    {
        int tp = tid & 63;
        int cg = tid >> 6;
#pragma unroll
        for (int cc = 0; cc < 6; cc++) {
            int ch = cg * 6 + cc;
            float s[18];
#pragma unroll
            for (int j = 0; j < 9; j++) {
                float2 v = *(const float2*)&sh[ch][2 * tp + 2 * j];
                s[2*j] = v.x; s[2*j+1] = v.y;
            }
            float a0 = 0.0f, a1 = 0.0f;
#pragma unroll
            for (int k = 0; k < 15; k++) {
                float w = sdw[ch][k];
                a0 = fmaf(s[k],     w, a0);
                a1 = fmaf(s[k + 1], w, a1);
            }
            *(float2*)&dwv[ch][2 * tp] = make_float2(a0, a1);
        }
    }
    __syncthreads();

    // pointwise: thread = (t = tid&127, o-group of 16)
    int tl = tid & 127;
    int og = tid >> 7;
    float dreg[24];
#pragma unroll
    for (int ch = 0; ch < 24; ch++) dreg[ch] = dwv[ch][tl];

    int t = t0 + tl;
#pragma unroll
    for (int oo = 0; oo < 16; oo++) {
        int o = og * 16 + oo;
        float a = 0.0f;
#pragma unroll
        for (int c4 = 0; c4 < 6; c4++) {
            float4 w = *(const float4*)&spw[o][c4 * 4];
            a = fmaf(dreg[c4*4+0], w.x, a);
            a = fmaf(dreg[c4*4+1], w.y, a);
            a = fmaf(dreg[c4*4+2], w.z, a);
            a = fmaf(dreg[c4*4+3], w.w, a);
        }
        g_pw[(size_t)o * BT + b * T + t] = a;
    }
}

// ---------------------------------------------------------------------------
// K_scan: phase0 own-slice BN1 partials + device barrier (64 co-resident
// blocks, self-resetting counters) + finalize + prelif + parallel cs/ts
// (8 chunk-warps, tau^32 Horner) + serial m + FC.
// ---------------------------------------------------------------------------
__global__ void __launch_bounds__(256)
k_scan(const float* __restrict__ bn1_g,
       const float* __restrict__ bn1_b,
       const float* __restrict__ tau_geo,
       const float* __restrict__ beta_m,
       const float* __restrict__ alpha,
       const float* __restrict__ gamma_p,
       const float* __restrict__ fcW,
       const float* __restrict__ fcb,
       float* __restrict__ out) {
    extern __shared__ float dsm[];
    float (*sx)[33]   = (float(*)[33])dsm;              // 8448 floats
    float (*svth)[33] = (float(*)[33])(dsm + 8448);     // 8448
    float* Lcs = dsm + 16896;                           // 256
    float* Lts = Lcs + 256;                             // 256
    float* ssc = Lts + 256;                             // 32
    float* ssh = ssc + 32;                              // 32

    int b   = blockIdx.x;
    int tid = threadIdx.x;
    int w   = tid >> 5, lane = tid & 31;

    // Phase 0: BN1 partials over this block's own b-slice (L2/L1 warm-up).
    {
        int o = tid >> 3, p = tid & 7;
        const float4* src = (const float4*)(g_pw + (size_t)o * BT + b * T);
        float s = 0.0f, q = 0.0f;
#pragma unroll 8
        for (int k = 0; k < 32; k++) {
            float4 v = src[p + 8 * k];
            s += v.x + v.y + v.z + v.w;
            q += v.x*v.x + v.y*v.y + v.z*v.z + v.w*v.w;
        }
#pragma unroll
        for (int off = 4; off > 0; off >>= 1) {
            s += __shfl_xor_sync(0xffffffffu, s, off);
            q += __shfl_xor_sync(0xffffffffu, q, off);
        }
        if (p == 0) { g_bps[b * 32 + o] = s; g_bpq[b * 32 + o] = q; }
    }
    __syncthreads();

    // Device barrier: all 64 blocks co-resident (64 <= #SMs). Self-resets.
    if (tid == 0) {
        __threadfence();
        atomicAdd(&g_ctr1, 1);
        while (*((volatile int*)&g_ctr1) < 64) { }
        __threadfence();
        int r = atomicAdd(&g_ctr2, 1);
        if (r == 63) {
            g_ctr2 = 0;
            __threadfence();
            g_ctr1 = 0;
        }
    }
    __syncthreads();

    // BN1 finalize (redundant per block, deterministic fixed order).
    {
        int ch = tid >> 3, p = tid & 7;
        float s = 0.0f, q = 0.0f;
#pragma unroll
        for (int j = 0; j < 8; j++) {
            int bb = p + 8 * j;
            s += g_bps[bb * 32 + ch];
            q += g_bpq[bb * 32 + ch];
        }
#pragma unroll
        for (int off = 4; off > 0; off >>= 1) {
            s += __shfl_xor_sync(0xffffffffu, s, off);
            q += __shfl_xor_sync(0xffffffffu, q, off);
        }
        if (p == 0) {
            float mean = s * (1.0f / BT);
            float var  = fmaxf(q * (1.0f / BT) - mean * mean, 0.0f);
            float sc   = bn1_g[ch] * rsqrtf(var + 1e-5f);
            ssc[ch] = sc;
            ssh[ch] = bn1_b[ch] - mean * sc;
        }
    }
    __syncthreads();

    float tau    = 1.0f / (1.0f + expf(-tau_geo[0]));
    float om_tau = 1.0f - tau;

    // prelif: BN1+ELU+pool4 -> sx[tq][o]
    {
        int o = tid >> 3, p = tid & 7;
        const float4* src = (const float4*)(g_pw + (size_t)o * BT + b * T);
        float sc = ssc[o], shf = ssh[o];
#pragma unroll 8
        for (int k = 0; k < 32; k++) {
            int tq = p + 8 * k;
            float4 v = src[tq];
            float y0 = eluf(fmaf(v.x, sc, shf));
            float y1 = eluf(fmaf(v.y, sc, shf));
            float y2 = eluf(fmaf(v.z, sc, shf));
            float y3 = eluf(fmaf(v.w, sc, shf));
            sx[tq][o] = (y0 + y1 + y2 + y3) * 0.25f;
        }
    }

    // Pass 1: chunk-local cs/ts (zero init). warp w = chunk, lane = o.
    const float* cup = g_curv + (size_t)b * (TQ * 32) + lane;
    const float* tap = g_tang + (size_t)b * (TQ * 32) + lane;
    {
        float cs = 0.0f, ts = 0.0f;
#pragma unroll
        for (int bk = 0; bk < 4; bk++) {
            float cu8[8], ta8[8];
#pragma unroll
            for (int j = 0; j < 8; j++) {
                int t = w * 32 + bk * 8 + j;
                cu8[j] = cup[t * 32];
                ta8[j] = tap[t * 32];
            }
#pragma unroll
            for (int j = 0; j < 8; j++) {
                cs = fmaf(tau, cs, om_tau * cu8[j]);
                ts = fmaf(tau, ts, om_tau * ta8[j]);
            }
        }
        Lcs[w * 32 + lane] = cs;
        Lts[w * 32 + lane] = ts;
    }
    __syncthreads();

    // Pass 2: true init via Horner, recompute, emit vth and x*sens.
    {
        float f32 = tau;
        f32 = f32 * f32; f32 = f32 * f32; f32 = f32 * f32;
        f32 = f32 * f32; f32 = f32 * f32;                     // tau^32

        float Ics = 0.0f, Its = 0.0f;
        for (int j = 0; j < w; j++) {
            Ics = fmaf(Ics, f32, Lcs[j * 32 + lane]);
            Its = fmaf(Its, f32, Lts[j * 32 + lane]);
        }

        float al = alpha[0];
        float gp = gamma_p[0];
        float cs = Ics, ts = Its;
#pragma unroll
        for (int bk = 0; bk < 4; bk++) {
            float cu8[8], ta8[8];
#pragma unroll
            for (int j = 0; j < 8; j++) {
                int t = w * 32 + bk * 8 + j;
                cu8[j] = cup[t * 32];
                ta8[j] = tap[t * 32];
            }
#pragma unroll
            for (int j = 0; j < 8; j++) {
                int t = w * 32 + bk * 8 + j;
                cs = fmaf(tau, cs, om_tau * cu8[j]);
                ts = fmaf(tau, ts, om_tau * ta8[j]);
                svth[t][lane] = fmaxf(fmaf(al, cs, 0.3f), 0.1f);
                float a    = fmaf(-gp, ts, 1.0f);
                float sens = 1.0f / (1.0f + __expf(-a));
                sx[t][lane] *= sens;
            }
        }
    }
    __syncthreads();

    // Serial m-loop (warp 0) + FC.
    if (tid < 32) {
        int o = tid;
        float beta = beta_m[0];
        float m = 0.0f, fr = 0.0f;
#pragma unroll 8
        for (int t = 0; t < TQ; t++) {
            float mn  = fmaf(beta, m, sx[t][o]);
            float dif = mn - svth[t][o];
            bool  sp  = dif > 0.0f;
            m = sp ? dif : mn;
            fr += sp ? 1.0f : 0.0f;
        }
        fr *= (1.0f / (float)TQ);

        float res[4];
#pragma unroll
        for (int k = 0; k < 4; k++) {
            float vv = fr * __ldg(fcW + k * 32 + o);
#pragma unroll
            for (int off = 16; off > 0; off >>= 1)
                vv += __shfl_xor_sync(0xffffffffu, vv, off);
            res[k] = vv;
        }
        if (o == 0) {
#pragma unroll
            for (int k = 0; k < 4; k++)
                out[b * 4 + k] = res[k] + __ldg(fcb + k);
        }
    }
}

// ---------------------------------------------------------------------------
extern "C" void kernel_launch(void* const* d_in, const int* in_sizes, int n_in,
                              void* d_out, int out_size) {
    const float* xb       = (const float*)d_in[0];
    const float* mu       = (const float*)d_in[1];
    const float* sigma    = (const float*)d_in[2];
    const float* curvW    = (const float*)d_in[3];
    const float* tangW    = (const float*)d_in[4];
    const float* spatialW = (const float*)d_in[5];
    const float* bn2_g    = (const float*)d_in[6];
    const float* bn2_b    = (const float*)d_in[7];
    const float* dwW      = (const float*)d_in[8];
    const float* pwW      = (const float*)d_in[9];
    const float* bn1_g    = (const float*)d_in[10];
    const float* bn1_b    = (const float*)d_in[11];
    const float* tau_geo  = (const float*)d_in[12];
    const float* beta_m   = (const float*)d_in[13];
    const float* alpha    = (const float*)d_in[14];
    const float* gamma_p  = (const float*)d_in[15];
    const float* fcW      = (const float*)d_in[16];
    const float* fcb      = (const float*)d_in[17];
    float* out            = (float*)d_out;

    static bool attr_set = false;
    const int scan_smem = (8448 * 2 + 512 + 64) * 4;   // 69888 B
    if (!attr_set) {
        cudaFuncSetAttribute(k_scan, cudaFuncAttributeMaxDynamicSharedMemorySize,
                             scan_smem);
        attr_set = true;
    }

    k_front<<<448, 256>>>(xb, curvW, tangW, mu, sigma, spatialW);
    k_conv<<<512, 256>>>(dwW, pwW, bn2_g, bn2_b);
    k_scan<<<64, 256, scan_smem>>>(bn1_g, bn1_b, tau_geo, beta_m, alpha,
                                   gamma_p, fcW, fcb, out);
}